// round 9
// baseline (speedup 1.0000x reference)
#include <cuda_runtime.h>
#include <cstdint>

// Problem constants
#define NB 8
#define RR 256
#define CI 64
#define CO 64
#define MD 16
#define KXN 32  // 16 top + 16 bottom kx modes

typedef unsigned long long u64;

// ---------------------------------------------------------------------------
// Scratch (device globals -- no allocation allowed)
// ---------------------------------------------------------------------------
__device__ float2 g_A[NB * MD * RR * CI];   // [b][ky][u][i]   16.8 MB
__device__ float2 g_F[NB * KXN * MD * CI];  // [b][kx][ky][i]   2.1 MB
__device__ float2 g_G[NB * KXN * MD * CO];  // [b][kx][ky][o]   2.1 MB
__device__ float2 g_H[NB * MD * RR * CO];   // [b][ky][u][o]   16.8 MB

// ---------------------------------------------------------------------------
// Packed f32x2 helpers (Blackwell dual-FP32 pipe; only reachable via PTX)
// ---------------------------------------------------------------------------
__device__ __forceinline__ u64 pack2(float lo, float hi) {
    u64 r;
    asm("mov.b64 %0, {%1,%2};" : "=l"(r) : "f"(lo), "f"(hi));
    return r;
}
__device__ __forceinline__ u64 fma2(u64 a, u64 b, u64 c) {
    u64 r;
    asm("fma.rn.f32x2 %0, %1, %2, %3;" : "=l"(r) : "l"(a), "l"(b), "l"(c));
    return r;
}
__device__ __forceinline__ u64 add2(u64 a, u64 b) {
    u64 r;
    asm("add.rn.f32x2 %0, %1, %2;" : "=l"(r) : "l"(a), "l"(b));
    return r;
}
__device__ __forceinline__ void unpack2(u64 v, float& lo, float& hi) {
    asm("mov.b64 {%0,%1}, %2;" : "=f"(lo), "=f"(hi) : "l"(v));
}

__device__ __forceinline__ float silu_f(float x) {
    float e = __expf(-x);
    return __fdividef(x, 1.0f + e);
}

// ---------------------------------------------------------------------------
// K1: partial column DFT along v for ky = 0..15. (R7 version, verified.)
// ---------------------------------------------------------------------------
__global__ __launch_bounds__(256) void k1_coldft(const float* __restrict__ X) {
    __shared__ u64 csd[256];  // (c, c)
    __shared__ u64 snd[256];  // (-s, -s)
    int tid = threadIdx.x;
    {
        float s, c;
        sincospif((float)tid * (1.0f / 128.0f), &s, &c);  // angle 2*pi*tid/256
        csd[tid] = pack2(c, c);
        snd[tid] = pack2(-s, -s);
    }
    __syncthreads();

    int u = blockIdx.x, b = blockIdx.y;
    int lane = tid & 31, g = tid >> 5;
    int ky0 = 2 * g, ky1 = 2 * g + 1;
    const u64* xr = (const u64*)(X + ((size_t)(b * RR + u) * RR) * CI) + lane;

    u64 one = pack2(1.0f, 1.0f), mone = pack2(-1.0f, -1.0f);
    u64 x0 = xr[0];
    u64 x128 = xr[128 * 32];
    u64 ar0 = fma2(x128, one, x0);   // ky even: x0 + x128
    u64 ar1 = fma2(x128, mone, x0);  // ky odd:  x0 - x128
    u64 ai0 = pack2(0.0f, 0.0f), ai1 = ai0;

    int t0 = 0, t1 = 0;
#pragma unroll 4
    for (int v = 1; v <= 127; ++v) {
        u64 xa = xr[v * 32];
        u64 xb = xr[(256 - v) * 32];
        u64 smv = add2(xa, xb);
        u64 dfv = fma2(xb, mone, xa);
        t0 = (t0 + ky0) & 255;  // ky0 * v
        t1 = (t1 + ky1) & 255;  // ky1 * v
        ar0 = fma2(smv, csd[t0], ar0);
        ai0 = fma2(dfv, snd[t0], ai0);
        ar1 = fma2(smv, csd[t1], ar1);
        ai1 = fma2(dfv, snd[t1], ai1);
    }

    float4* a4 = (float4*)g_A;
    float rl, rh, il, ih;
    unpack2(ar0, rl, rh); unpack2(ai0, il, ih);
    a4[((size_t)(b * MD + ky0) * RR + u) * 32 + lane] = make_float4(rl, il, rh, ih);
    unpack2(ar1, rl, rh); unpack2(ai1, il, ih);
    a4[((size_t)(b * MD + ky1) * RR + u) * 32 + lane] = make_float4(rl, il, rh, ih);
}

// ---------------------------------------------------------------------------
// K2: partial row DFT along u, conjugate-paired modes + Chebyshev twiddles.
// Modes kx in {0..15, 240..255}; kx = 256-k is the conjugate of kx = k, so
// with P = sum prs*c_k, Q = sum mis*s_k, R = sum pis*c_k, S = sum mrs*s_k:
//   top (m=k):     F = (P+Q, R-S)      bottom (m=32-k): F = (P-Q, R+S)
// c_k, s_k via Chebyshev recurrence (no tables, no index ALU in inner loop).
// Thread = (channel i, u-split g in 0..3); smem reduction; u=0/128 terms
// folded in during the reduce phase.
// Dynamic smem: parts[4][17][4][64] floats | tw float2[256]
// ---------------------------------------------------------------------------
#define K2_TW (4 * 17 * 4 * 64)        // 17408 floats
#define K2_TOT (K2_TW + 512)           // 17920 floats = 71680 bytes

__global__ __launch_bounds__(256) void k2_rowdft() {
    extern __shared__ float s2[];
    float* part = s2;                  // [g][k][w][i]
    float2* tw = (float2*)(s2 + K2_TW);
    int tid = threadIdx.x;
    {
        float s, c;
        sincospif((float)tid * (1.0f / 128.0f), &s, &c);
        tw[tid] = make_float2(c, s);
    }
    __syncthreads();

    int ky = blockIdx.x, b = blockIdx.y;
    int i = tid & 63, g = tid >> 6;
    const float2* ap = g_A + ((size_t)(b * MD + ky) * RR) * CI + i;

    float P[17], Q[17], R[17], S[17];
#pragma unroll
    for (int k = 0; k < 17; k++) { P[k] = 0.f; Q[k] = 0.f; R[k] = 0.f; S[k] = 0.f; }

    // u = g+1+4t covers {1..127} exactly once across g=0..3 (g=3,t=31 -> 128 excluded)
#pragma unroll 2
    for (int t = 0; t < 32; t++) {
        int u = g + 1 + 4 * t;
        if (u > 127) break;
        float2 aa = ap[u * CI];
        float2 ab = ap[(256 - u) * CI];
        float prs = aa.x + ab.x, mrs = aa.x - ab.x;
        float pis = aa.y + ab.y, mis = aa.y - ab.y;
        float2 w1 = tw[u];
        float c1 = w1.x, s1 = w1.y;
        float tc = 2.0f * c1;
        P[0] += prs; R[0] += pis;
        P[1] += prs * c1; Q[1] += mis * s1;
        R[1] += pis * c1; S[1] += mrs * s1;
        float ckm2 = 1.0f, skm2 = 0.0f;
        float ckm1 = c1, skm1 = s1;
#pragma unroll
        for (int k = 2; k <= 16; k++) {
            float ck = tc * ckm1 - ckm2;
            float sk = tc * skm1 - skm2;
            P[k] += prs * ck; Q[k] += mis * sk;
            R[k] += pis * ck; S[k] += mrs * sk;
            ckm2 = ckm1; ckm1 = ck;
            skm2 = skm1; skm1 = sk;
        }
    }

    // Store partials: part[((g*17 + k)*4 + w)*64 + i]
    {
        float* pb = part + (size_t)(g * 17) * 4 * 64 + i;
#pragma unroll
        for (int k = 0; k <= 16; k++) {
            pb[(k * 4 + 0) * 64] = P[k];
            pb[(k * 4 + 1) * 64] = Q[k];
            pb[(k * 4 + 2) * 64] = R[k];
            pb[(k * 4 + 3) * 64] = S[k];
        }
    }
    __syncthreads();

    // Reduce 4 splits, add u=0 / u=128 terms, combine to top/bottom modes.
    for (int p = tid; p < 17 * 64; p += 256) {
        int k = p >> 6, ii = p & 63;
        float Pp = 0.f, Qq = 0.f, Rr = 0.f, Ss = 0.f;
#pragma unroll
        for (int gg = 0; gg < 4; gg++) {
            const float* q = part + (size_t)((gg * 17 + k) * 4) * 64 + ii;
            Pp += q[0]; Qq += q[64]; Rr += q[128]; Ss += q[192];
        }
        const float2* ap2 = g_A + ((size_t)(b * MD + ky) * RR) * CI + ii;
        float2 a0 = ap2[0];
        float2 a128 = ap2[128 * CI];
        float sg = (k & 1) ? -1.0f : 1.0f;
        Pp += a0.x + sg * a128.x;
        Rr += a0.y + sg * a128.y;
        if (k <= 15)
            g_F[(((size_t)(b * KXN + k) * MD) + ky) * CI + ii] = make_float2(Pp + Qq, Rr - Ss);
        if (k >= 1)
            g_F[(((size_t)(b * KXN + (32 - k)) * MD) + ky) * CI + ii] = make_float2(Pp - Qq, Rr + Ss);
    }
}

// ---------------------------------------------------------------------------
// K3: channel mix (complex einsum over input channels) + ortho-norm fold.
// (R7 version, verified.)
// ---------------------------------------------------------------------------
__global__ __launch_bounds__(256) void k3_mix(const float* __restrict__ fw0,
                                              const float* __restrict__ fw1) {
    __shared__ float2 ws[CI * CO];   // 32 KB
    __shared__ float2 fs[NB][CI];    // 4 KB
    int tid = threadIdx.x;
    int kxi = blockIdx.x, ky = blockIdx.y;
    const float* src = (kxi < 16) ? fw0 : fw1;
    int x = (kxi < 16) ? kxi : (kxi - 16);

    for (int p = tid; p < CI * CO; p += 256) {
        int i = p >> 6, o = p & 63;
        ws[p] = *(const float2*)(src + ((((size_t)i * CO + o) * MD + x) * MD + ky) * 2);
    }
    for (int p = tid; p < NB * CI; p += 256) {
        int bb = p >> 6, i = p & 63;
        fs[bb][i] = g_F[(((size_t)(bb * KXN + kxi) * MD) + ky) * CI + i];
    }
    __syncthreads();

    int o = tid & 63, bg = tid >> 6;
    const float scale = 1.0f / 65536.0f;  // ortho norm (1/256 fwd * 1/256 inv)
    for (int bb = bg; bb < NB; bb += 4) {
        float Gr = 0.f, Gi = 0.f;
#pragma unroll 8
        for (int i = 0; i < CI; i++) {
            float2 f = fs[bb][i];
            float2 w = ws[i * CO + o];
            Gr += f.x * w.x - f.y * w.y;
            Gi += f.x * w.y + f.y * w.x;
        }
        g_G[(((size_t)(bb * KXN + kxi) * MD) + ky) * CO + o] =
            make_float2(Gr * scale, Gi * scale);
    }
}

// ---------------------------------------------------------------------------
// K4: inverse DFT along kx, conjugate-paired modes + u-pair symmetry +
// Chebyshev twiddles.
//   H(u)  = sum_k Sx*c_k - Dy*s_k  + i (Sy*c_k + Dx*s_k)
//   H(-u) = sum_k Sx*c_k + Dy*s_k  + i (Sy*c_k - Dx*s_k)
// where Sx = Gt.x+Gb.x, Sy = Gt.y+Gb.y, Dy = Gt.y-Gb.y, Dx = Gt.x-Gb.x
// (Gt = top mode k<=15, Gb = bottom mode idx 32-k for k>=1), precomputed in
// smem. 4 FMAs per k produce TWO u outputs; c_k/s_k via Chebyshev (2 FMAs,
// zero LDS/ALU). u_lo = 0..127 split across 4 grps x 4 z; u=128 handled by
// the base==0 threads as a 9th iteration (tw[128]=(-1,0) works in the same
// code path; self-mirror writes are identical).
// ---------------------------------------------------------------------------
__global__ __launch_bounds__(256) void k4_invrow() {
    __shared__ float2 tw[256];
    __shared__ float2 a1[17 * 64];   // (Sx, Sy)
    __shared__ float2 a2[17 * 64];   // (Dy, Dx)
    int tid = threadIdx.x;
    {
        float s, c;
        sincospif((float)tid * (1.0f / 128.0f), &s, &c);
        tw[tid] = make_float2(c, s);
    }
    int ky = blockIdx.x, b = blockIdx.y;
    const float2* gp = g_G + ((size_t)(b * KXN) * MD + ky) * CO;  // idx stride MD*CO
    for (int p = tid; p < 17 * 64; p += 256) {
        int k = p >> 6, o = p & 63;
        float2 gt = (k < 16) ? gp[(size_t)k * MD * CO + o] : make_float2(0.f, 0.f);
        float2 gb = (k >= 1) ? gp[(size_t)(32 - k) * MD * CO + o] : make_float2(0.f, 0.f);
        a1[p] = make_float2(gt.x + gb.x, gt.y + gb.y);
        a2[p] = make_float2(gt.y - gb.y, gt.x - gb.x);
    }
    __syncthreads();

    int o = tid & 63, grp = tid >> 6;
    int base = blockIdx.z * 32 + grp * 8;
    int nIter = (base == 0) ? 9 : 8;     // warp-uniform (tid<64 of z==0)
    float2* hp = g_H + ((size_t)(b * MD + ky) * RR) * CO + o;
    const float2* a1p = a1 + o;
    const float2* a2p = a2 + o;

#pragma unroll 2
    for (int it = 0; it < nIter; it++) {
        int u = (it == 8) ? 128 : (base + it);
        float2 w1 = tw[u];
        float c1 = w1.x, s1 = w1.y;
        float tc = 2.0f * c1;
        float2 v0 = a1p[0];
        float Pc = v0.x, Qc = v0.y, Ps = 0.f, Qs = 0.f;
        float2 x1 = a1p[64], y1 = a2p[64];
        Pc += x1.x * c1; Qc += x1.y * c1;
        Ps += y1.x * s1; Qs += y1.y * s1;
        float ckm2 = 1.f, ckm1 = c1, skm2 = 0.f, skm1 = s1;
#pragma unroll
        for (int k = 2; k <= 16; k++) {
            float ck = tc * ckm1 - ckm2;
            float sk = tc * skm1 - skm2;
            float2 xk = a1p[k * 64], yk = a2p[k * 64];
            Pc += xk.x * ck; Qc += xk.y * ck;
            Ps += yk.x * sk; Qs += yk.y * sk;
            ckm2 = ckm1; ckm1 = ck;
            skm2 = skm1; skm1 = sk;
        }
        int um = (u == 0) ? 0 : (256 - u);
        hp[(size_t)u * CO]  = make_float2(Pc - Ps, Qc + Qs);
        hp[(size_t)um * CO] = make_float2(Pc + Ps, Qc - Qs);
    }
}

// ---------------------------------------------------------------------------
// K5: fused inverse real-DFT along ky + residual GEMM + SiLU.
// (R7 version, verified.)
// ---------------------------------------------------------------------------
#define XP_STRIDE 67
#define F_BASE (128 * XP_STRIDE * 2)         // float index 17152
#define SM5_HR F_BASE
#define SM5_HI (SM5_HR + MD * CO)
#define SM5_CS (SM5_HI + MD * CO)
#define SM5_NS (SM5_CS + 256)
#define SM5_WS (SM5_NS + 256)
#define SM5_BR (SM5_WS + 4096)
#define SM5_TOT (SM5_BR + 64)                // 23872 floats = 95488 bytes

__global__ __launch_bounds__(256, 2) void k5_final(const float* __restrict__ X,
                                                   const float* __restrict__ Wres,
                                                   const float* __restrict__ bres,
                                                   float* __restrict__ out) {
    extern __shared__ float sm[];
    u64* Xp = (u64*)sm;
    float* Hr = sm + SM5_HR;
    float* Hi = sm + SM5_HI;
    float* cs2 = sm + SM5_CS;
    float* ns2 = sm + SM5_NS;
    float* Ws = sm + SM5_WS;
    float* br = sm + SM5_BR;

    int tid = threadIdx.x;
    int u = blockIdx.x, b = blockIdx.y;

    {
        float s, c;
        sincospif((float)tid * (1.0f / 128.0f), &s, &c);
        cs2[tid] = 2.0f * c;   // factor 2 folded (Hermitian pairs)
        ns2[tid] = -2.0f * s;
    }
    if (tid < 64) br[tid] = bres[tid];
    {
        const float4* w4 = (const float4*)Wres;
        float4* ws4 = (float4*)Ws;
        for (int p = tid; p < 1024; p += 256) ws4[p] = w4[p];
    }
    {
        // Xpair[vp][c] = (X[2vp][c], X[2vp+1][c]) as u64, stride XP_STRIDE.
        const float4* x4 = (const float4*)(X + ((size_t)(b * RR + u) * RR) * CI);
        for (int p = tid; p < 4096; p += 256) {
            float4 xv = x4[p];
            int v = p >> 4;            // 16 float4 per v-row
            int cq = (p & 15) * 4;
            float* base = (float*)(Xp + (size_t)(v >> 1) * XP_STRIDE + cq) + (v & 1);
            base[0] = xv.x; base[2] = xv.y; base[4] = xv.z; base[6] = xv.w;
        }
    }
    for (int p = tid; p < MD * CO; p += 256) {
        int ky = p >> 6, o = p & 63;
        float2 h = g_H[(((size_t)(b * MD + ky) * RR) + u) * CO + o];
        Hr[p] = h.x;
        Hi[p] = h.y;
    }
    __syncthreads();

    int vg = tid >> 3, og = tid & 7;
    int v0 = vg * 8, o0 = og * 8;
    int vp0 = vg * 4;

    unsigned long long acc[4][8];
#pragma unroll
    for (int k = 0; k < 8; k++) {
        u64 bb = pack2(br[o0 + k], br[o0 + k]);
#pragma unroll
        for (int p = 0; p < 4; p++) acc[p][k] = bb;
    }

    // Residual GEMM: acc[p][k] over v-pair (vp0+p) x o (o0+k)
    const u64* xb = Xp + (size_t)vp0 * XP_STRIDE;
#pragma unroll 4
    for (int c = 0; c < CI; c++) {
        u64 xp0 = xb[c];
        u64 xp1 = xb[XP_STRIDE + c];
        u64 xp2 = xb[2 * XP_STRIDE + c];
        u64 xp3 = xb[3 * XP_STRIDE + c];
        const float* wr = Ws + c * 64 + o0;
        float4 wa = *(const float4*)wr;
        float4 wb = *(const float4*)(wr + 4);
        float wv[8] = {wa.x, wa.y, wa.z, wa.w, wb.x, wb.y, wb.z, wb.w};
#pragma unroll
        for (int k = 0; k < 8; k++) {
            u64 wd = pack2(wv[k], wv[k]);
            acc[0][k] = fma2(xp0, wd, acc[0][k]);
            acc[1][k] = fma2(xp1, wd, acc[1][k]);
            acc[2][k] = fma2(xp2, wd, acc[2][k]);
            acc[3][k] = fma2(xp3, wd, acc[3][k]);
        }
    }

    // Spectral ky = 0 term: + Re(H0[o]) (DC imag discarded, matches irfft)
#pragma unroll
    for (int k = 0; k < 8; k++) {
        u64 h0 = pack2(Hr[o0 + k], Hr[o0 + k]);
#pragma unroll
        for (int p = 0; p < 4; p++) acc[p][k] = add2(acc[p][k], h0);
    }

    // Spectral ky = 1..15: + 2*(Hr*cos - Hi*sin)
    for (int ky = 1; ky < MD; ky++) {
        u64 cp[4], sp[4];
#pragma unroll
        for (int p = 0; p < 4; p++) {
            int ta = (ky * (v0 + 2 * p)) & 255;
            int tb = (ta + ky) & 255;
            cp[p] = pack2(cs2[ta], cs2[tb]);
            sp[p] = pack2(ns2[ta], ns2[tb]);
        }
        const float* hrp = Hr + ky * 64 + o0;
        const float* hip = Hi + ky * 64 + o0;
#pragma unroll
        for (int k = 0; k < 8; k++) {
            u64 hrd = pack2(hrp[k], hrp[k]);
            u64 hid = pack2(hip[k], hip[k]);
#pragma unroll
            for (int p = 0; p < 4; p++) {
                acc[p][k] = fma2(hrd, cp[p], acc[p][k]);
                acc[p][k] = fma2(hid, sp[p], acc[p][k]);
            }
        }
    }

    // SiLU + store (float4)
    float* ob = out + (((size_t)(b * RR + u) * RR) + v0) * CO + o0;
#pragma unroll
    for (int p = 0; p < 4; p++) {
        float lo[8], hi[8];
#pragma unroll
        for (int k = 0; k < 8; k++) unpack2(acc[p][k], lo[k], hi[k]);
        float* r0 = ob + (size_t)(2 * p) * CO;
        float* r1 = ob + (size_t)(2 * p + 1) * CO;
        *(float4*)r0 = make_float4(silu_f(lo[0]), silu_f(lo[1]), silu_f(lo[2]), silu_f(lo[3]));
        *(float4*)(r0 + 4) = make_float4(silu_f(lo[4]), silu_f(lo[5]), silu_f(lo[6]), silu_f(lo[7]));
        *(float4*)r1 = make_float4(silu_f(hi[0]), silu_f(hi[1]), silu_f(hi[2]), silu_f(hi[3]));
        *(float4*)(r1 + 4) = make_float4(silu_f(hi[4]), silu_f(hi[5]), silu_f(hi[6]), silu_f(hi[7]));
    }
}

// ---------------------------------------------------------------------------
// Launcher
// ---------------------------------------------------------------------------
extern "C" void kernel_launch(void* const* d_in, const int* in_sizes, int n_in,
                              void* d_out, int out_size) {
    const float* X = (const float*)d_in[0];
    const float* Wres = (const float*)d_in[1];
    const float* bres = (const float*)d_in[2];
    const float* fw0 = (const float*)d_in[3];
    const float* fw1 = (const float*)d_in[4];
    float* out = (float*)d_out;

    cudaFuncSetAttribute(k2_rowdft, cudaFuncAttributeMaxDynamicSharedMemorySize,
                         K2_TOT * (int)sizeof(float));
    cudaFuncSetAttribute(k5_final, cudaFuncAttributeMaxDynamicSharedMemorySize,
                         SM5_TOT * (int)sizeof(float));

    k1_coldft<<<dim3(RR, NB), 256>>>(X);
    k2_rowdft<<<dim3(MD, NB), 256, K2_TOT * (int)sizeof(float)>>>();
    k3_mix<<<dim3(KXN, MD), 256>>>(fw0, fw1);
    k4_invrow<<<dim3(MD, NB, 4), 256>>>();
    k5_final<<<dim3(RR, NB), 256, SM5_TOT * (int)sizeof(float)>>>(X, Wres, bres, out);
}

// round 10
// speedup vs baseline: 1.2895x; 1.2895x over previous
#include <cuda_runtime.h>
#include <cstdint>

// Problem constants
#define NB 8
#define RR 256
#define CI 64
#define CO 64
#define MD 16
#define KXN 32  // 16 top + 16 bottom kx modes

typedef unsigned long long u64;

// ---------------------------------------------------------------------------
// Scratch (device globals -- no allocation allowed)
// ---------------------------------------------------------------------------
__device__ float2 g_A[NB * MD * RR * CI];   // [b][ky][u][i]   16.8 MB
__device__ float2 g_F[NB * KXN * MD * CI];  // [b][kx][ky][i]   2.1 MB
__device__ float2 g_G[NB * KXN * MD * CO];  // [b][kx][ky][o]   2.1 MB
__device__ float2 g_H[NB * MD * RR * CO];   // [b][ky][u][o]   16.8 MB

// ---------------------------------------------------------------------------
// Packed f32x2 helpers (Blackwell dual-FP32 pipe; only reachable via PTX)
// ---------------------------------------------------------------------------
__device__ __forceinline__ u64 pack2(float lo, float hi) {
    u64 r;
    asm("mov.b64 %0, {%1,%2};" : "=l"(r) : "f"(lo), "f"(hi));
    return r;
}
__device__ __forceinline__ u64 fma2(u64 a, u64 b, u64 c) {
    u64 r;
    asm("fma.rn.f32x2 %0, %1, %2, %3;" : "=l"(r) : "l"(a), "l"(b), "l"(c));
    return r;
}
__device__ __forceinline__ u64 add2(u64 a, u64 b) {
    u64 r;
    asm("add.rn.f32x2 %0, %1, %2;" : "=l"(r) : "l"(a), "l"(b));
    return r;
}
__device__ __forceinline__ void unpack2(u64 v, float& lo, float& hi) {
    asm("mov.b64 {%0,%1}, %2;" : "=f"(lo), "=f"(hi) : "l"(v));
}

__device__ __forceinline__ float silu_f(float x) {
    float e = __expf(-x);
    return __fdividef(x, 1.0f + e);
}

// ---------------------------------------------------------------------------
// K1: partial column DFT along v for ky = 0..15. (R7 version, verified.)
// ---------------------------------------------------------------------------
__global__ __launch_bounds__(256) void k1_coldft(const float* __restrict__ X) {
    __shared__ u64 csd[256];  // (c, c)
    __shared__ u64 snd[256];  // (-s, -s)
    int tid = threadIdx.x;
    {
        float s, c;
        sincospif((float)tid * (1.0f / 128.0f), &s, &c);  // angle 2*pi*tid/256
        csd[tid] = pack2(c, c);
        snd[tid] = pack2(-s, -s);
    }
    __syncthreads();

    int u = blockIdx.x, b = blockIdx.y;
    int lane = tid & 31, g = tid >> 5;
    int ky0 = 2 * g, ky1 = 2 * g + 1;
    const u64* xr = (const u64*)(X + ((size_t)(b * RR + u) * RR) * CI) + lane;

    u64 one = pack2(1.0f, 1.0f), mone = pack2(-1.0f, -1.0f);
    u64 x0 = xr[0];
    u64 x128 = xr[128 * 32];
    u64 ar0 = fma2(x128, one, x0);   // ky even: x0 + x128
    u64 ar1 = fma2(x128, mone, x0);  // ky odd:  x0 - x128
    u64 ai0 = pack2(0.0f, 0.0f), ai1 = ai0;

    int t0 = 0, t1 = 0;
#pragma unroll 4
    for (int v = 1; v <= 127; ++v) {
        u64 xa = xr[v * 32];
        u64 xb = xr[(256 - v) * 32];
        u64 smv = add2(xa, xb);
        u64 dfv = fma2(xb, mone, xa);
        t0 = (t0 + ky0) & 255;  // ky0 * v
        t1 = (t1 + ky1) & 255;  // ky1 * v
        ar0 = fma2(smv, csd[t0], ar0);
        ai0 = fma2(dfv, snd[t0], ai0);
        ar1 = fma2(smv, csd[t1], ar1);
        ai1 = fma2(dfv, snd[t1], ai1);
    }

    float4* a4 = (float4*)g_A;
    float rl, rh, il, ih;
    unpack2(ar0, rl, rh); unpack2(ai0, il, ih);
    a4[((size_t)(b * MD + ky0) * RR + u) * 32 + lane] = make_float4(rl, il, rh, ih);
    unpack2(ar1, rl, rh); unpack2(ai1, il, ih);
    a4[((size_t)(b * MD + ky1) * RR + u) * 32 + lane] = make_float4(rl, il, rh, ih);
}

// ---------------------------------------------------------------------------
// K2: partial row DFT along u for kx in {0..15, 240..255}.
// F[b][kxidx][ky][i] = sum_u A[b,ky,u,i] * exp(-2*pi*i*kx*u/256)
// u <-> 256-u symmetry with shared complex sum/diff.
// (R7-verified version: 4 modes/thread, z-split x2. The R9 Chebyshev
// rewrite spilled 68+ accumulators to local memory and is reverted.)
// ---------------------------------------------------------------------------
__global__ __launch_bounds__(256) void k2_rowdft() {
    __shared__ float cs[256], sn[256];
    int tid = threadIdx.x;
    {
        float s, c;
        sincospif((float)tid * (1.0f / 128.0f), &s, &c);
        cs[tid] = c;
        sn[tid] = s;
    }
    __syncthreads();

    int ky = blockIdx.x, b = blockIdx.y, z = blockIdx.z;
    int i = tid & 63, g = tid >> 6;     // g in 0..3
    int m0 = z * 16 + g * 4;            // this thread's 4 kxidx values
    const float2* ap = g_A + ((size_t)(b * MD + ky) * RR) * CI + i;

    float Fr[4], Fi[4];
    float2 a0 = ap[0];
    float2 a128 = ap[128 * CI];
    int kxv[4];
#pragma unroll
    for (int m = 0; m < 4; m++) {
        int idx = m0 + m;
        kxv[m] = (idx < 16) ? idx : (224 + idx);  // 240..255
        float sgn = (idx & 1) ? -1.0f : 1.0f;
        Fr[m] = a0.x + sgn * a128.x;
        Fi[m] = a0.y + sgn * a128.y;
    }

#pragma unroll 4
    for (int uu = 1; uu <= 127; ++uu) {
        float2 aa = ap[uu * CI];
        float2 ab = ap[(256 - uu) * CI];
        float prs = aa.x + ab.x, mrs = aa.x - ab.x;
        float pis = aa.y + ab.y, mis = aa.y - ab.y;
#pragma unroll
        for (int m = 0; m < 4; m++) {
            int t = (kxv[m] * uu) & 255;
            float c = cs[t], s = sn[t];
            Fr[m] += prs * c + mis * s;
            Fi[m] += pis * c - mrs * s;
        }
    }

#pragma unroll
    for (int m = 0; m < 4; m++) {
        g_F[(((size_t)(b * KXN + m0 + m) * MD) + ky) * CI + i] = make_float2(Fr[m], Fi[m]);
    }
}

// ---------------------------------------------------------------------------
// K3: channel mix (complex einsum over input channels) + ortho-norm fold.
// (R7 version, verified.)
// ---------------------------------------------------------------------------
__global__ __launch_bounds__(256) void k3_mix(const float* __restrict__ fw0,
                                              const float* __restrict__ fw1) {
    __shared__ float2 ws[CI * CO];   // 32 KB
    __shared__ float2 fs[NB][CI];    // 4 KB
    int tid = threadIdx.x;
    int kxi = blockIdx.x, ky = blockIdx.y;
    const float* src = (kxi < 16) ? fw0 : fw1;
    int x = (kxi < 16) ? kxi : (kxi - 16);

    for (int p = tid; p < CI * CO; p += 256) {
        int i = p >> 6, o = p & 63;
        ws[p] = *(const float2*)(src + ((((size_t)i * CO + o) * MD + x) * MD + ky) * 2);
    }
    for (int p = tid; p < NB * CI; p += 256) {
        int bb = p >> 6, i = p & 63;
        fs[bb][i] = g_F[(((size_t)(bb * KXN + kxi) * MD) + ky) * CI + i];
    }
    __syncthreads();

    int o = tid & 63, bg = tid >> 6;
    const float scale = 1.0f / 65536.0f;  // ortho norm (1/256 fwd * 1/256 inv)
    for (int bb = bg; bb < NB; bb += 4) {
        float Gr = 0.f, Gi = 0.f;
#pragma unroll 8
        for (int i = 0; i < CI; i++) {
            float2 f = fs[bb][i];
            float2 w = ws[i * CO + o];
            Gr += f.x * w.x - f.y * w.y;
            Gi += f.x * w.y + f.y * w.x;
        }
        g_G[(((size_t)(bb * KXN + kxi) * MD) + ky) * CO + o] =
            make_float2(Gr * scale, Gi * scale);
    }
}

// ---------------------------------------------------------------------------
// K4: inverse DFT along kx, conjugate-paired modes + u-pair symmetry +
// Chebyshev twiddles. (R9 version, verified 19.1us.)
//   H(u)  = sum_k Sx*c_k - Dy*s_k  + i (Sy*c_k + Dx*s_k)
//   H(-u) = sum_k Sx*c_k + Dy*s_k  + i (Sy*c_k - Dx*s_k)
// ---------------------------------------------------------------------------
__global__ __launch_bounds__(256) void k4_invrow() {
    __shared__ float2 tw[256];
    __shared__ float2 a1[17 * 64];   // (Sx, Sy)
    __shared__ float2 a2[17 * 64];   // (Dy, Dx)
    int tid = threadIdx.x;
    {
        float s, c;
        sincospif((float)tid * (1.0f / 128.0f), &s, &c);
        tw[tid] = make_float2(c, s);
    }
    int ky = blockIdx.x, b = blockIdx.y;
    const float2* gp = g_G + ((size_t)(b * KXN) * MD + ky) * CO;  // idx stride MD*CO
    for (int p = tid; p < 17 * 64; p += 256) {
        int k = p >> 6, o = p & 63;
        float2 gt = (k < 16) ? gp[(size_t)k * MD * CO + o] : make_float2(0.f, 0.f);
        float2 gb = (k >= 1) ? gp[(size_t)(32 - k) * MD * CO + o] : make_float2(0.f, 0.f);
        a1[p] = make_float2(gt.x + gb.x, gt.y + gb.y);
        a2[p] = make_float2(gt.y - gb.y, gt.x - gb.x);
    }
    __syncthreads();

    int o = tid & 63, grp = tid >> 6;
    int base = blockIdx.z * 32 + grp * 8;
    int nIter = (base == 0) ? 9 : 8;     // warp-uniform (tid<64 of z==0)
    float2* hp = g_H + ((size_t)(b * MD + ky) * RR) * CO + o;
    const float2* a1p = a1 + o;
    const float2* a2p = a2 + o;

#pragma unroll 2
    for (int it = 0; it < nIter; it++) {
        int u = (it == 8) ? 128 : (base + it);
        float2 w1 = tw[u];
        float c1 = w1.x, s1 = w1.y;
        float tc = 2.0f * c1;
        float2 v0 = a1p[0];
        float Pc = v0.x, Qc = v0.y, Ps = 0.f, Qs = 0.f;
        float2 x1 = a1p[64], y1 = a2p[64];
        Pc += x1.x * c1; Qc += x1.y * c1;
        Ps += y1.x * s1; Qs += y1.y * s1;
        float ckm2 = 1.f, ckm1 = c1, skm2 = 0.f, skm1 = s1;
#pragma unroll
        for (int k = 2; k <= 16; k++) {
            float ck = tc * ckm1 - ckm2;
            float sk = tc * skm1 - skm2;
            float2 xk = a1p[k * 64], yk = a2p[k * 64];
            Pc += xk.x * ck; Qc += xk.y * ck;
            Ps += yk.x * sk; Qs += yk.y * sk;
            ckm2 = ckm1; ckm1 = ck;
            skm2 = skm1; skm1 = sk;
        }
        int um = (u == 0) ? 0 : (256 - u);
        hp[(size_t)u * CO]  = make_float2(Pc - Ps, Qc + Qs);
        hp[(size_t)um * CO] = make_float2(Pc + Ps, Qc - Qs);
    }
}

// ---------------------------------------------------------------------------
// K5: fused inverse real-DFT along ky + residual GEMM + SiLU.
// (R7 version, verified.)
// ---------------------------------------------------------------------------
#define XP_STRIDE 67
#define F_BASE (128 * XP_STRIDE * 2)         // float index 17152
#define SM5_HR F_BASE
#define SM5_HI (SM5_HR + MD * CO)
#define SM5_CS (SM5_HI + MD * CO)
#define SM5_NS (SM5_CS + 256)
#define SM5_WS (SM5_NS + 256)
#define SM5_BR (SM5_WS + 4096)
#define SM5_TOT (SM5_BR + 64)                // 23872 floats = 95488 bytes

__global__ __launch_bounds__(256, 2) void k5_final(const float* __restrict__ X,
                                                   const float* __restrict__ Wres,
                                                   const float* __restrict__ bres,
                                                   float* __restrict__ out) {
    extern __shared__ float sm[];
    u64* Xp = (u64*)sm;
    float* Hr = sm + SM5_HR;
    float* Hi = sm + SM5_HI;
    float* cs2 = sm + SM5_CS;
    float* ns2 = sm + SM5_NS;
    float* Ws = sm + SM5_WS;
    float* br = sm + SM5_BR;

    int tid = threadIdx.x;
    int u = blockIdx.x, b = blockIdx.y;

    {
        float s, c;
        sincospif((float)tid * (1.0f / 128.0f), &s, &c);
        cs2[tid] = 2.0f * c;   // factor 2 folded (Hermitian pairs)
        ns2[tid] = -2.0f * s;
    }
    if (tid < 64) br[tid] = bres[tid];
    {
        const float4* w4 = (const float4*)Wres;
        float4* ws4 = (float4*)Ws;
        for (int p = tid; p < 1024; p += 256) ws4[p] = w4[p];
    }
    {
        // Xpair[vp][c] = (X[2vp][c], X[2vp+1][c]) as u64, stride XP_STRIDE.
        const float4* x4 = (const float4*)(X + ((size_t)(b * RR + u) * RR) * CI);
        for (int p = tid; p < 4096; p += 256) {
            float4 xv = x4[p];
            int v = p >> 4;            // 16 float4 per v-row
            int cq = (p & 15) * 4;
            float* base = (float*)(Xp + (size_t)(v >> 1) * XP_STRIDE + cq) + (v & 1);
            base[0] = xv.x; base[2] = xv.y; base[4] = xv.z; base[6] = xv.w;
        }
    }
    for (int p = tid; p < MD * CO; p += 256) {
        int ky = p >> 6, o = p & 63;
        float2 h = g_H[(((size_t)(b * MD + ky) * RR) + u) * CO + o];
        Hr[p] = h.x;
        Hi[p] = h.y;
    }
    __syncthreads();

    int vg = tid >> 3, og = tid & 7;
    int v0 = vg * 8, o0 = og * 8;
    int vp0 = vg * 4;

    unsigned long long acc[4][8];
#pragma unroll
    for (int k = 0; k < 8; k++) {
        u64 bb = pack2(br[o0 + k], br[o0 + k]);
#pragma unroll
        for (int p = 0; p < 4; p++) acc[p][k] = bb;
    }

    // Residual GEMM: acc[p][k] over v-pair (vp0+p) x o (o0+k)
    const u64* xb = Xp + (size_t)vp0 * XP_STRIDE;
#pragma unroll 4
    for (int c = 0; c < CI; c++) {
        u64 xp0 = xb[c];
        u64 xp1 = xb[XP_STRIDE + c];
        u64 xp2 = xb[2 * XP_STRIDE + c];
        u64 xp3 = xb[3 * XP_STRIDE + c];
        const float* wr = Ws + c * 64 + o0;
        float4 wa = *(const float4*)wr;
        float4 wb = *(const float4*)(wr + 4);
        float wv[8] = {wa.x, wa.y, wa.z, wa.w, wb.x, wb.y, wb.z, wb.w};
#pragma unroll
        for (int k = 0; k < 8; k++) {
            u64 wd = pack2(wv[k], wv[k]);
            acc[0][k] = fma2(xp0, wd, acc[0][k]);
            acc[1][k] = fma2(xp1, wd, acc[1][k]);
            acc[2][k] = fma2(xp2, wd, acc[2][k]);
            acc[3][k] = fma2(xp3, wd, acc[3][k]);
        }
    }

    // Spectral ky = 0 term: + Re(H0[o]) (DC imag discarded, matches irfft)
#pragma unroll
    for (int k = 0; k < 8; k++) {
        u64 h0 = pack2(Hr[o0 + k], Hr[o0 + k]);
#pragma unroll
        for (int p = 0; p < 4; p++) acc[p][k] = add2(acc[p][k], h0);
    }

    // Spectral ky = 1..15: + 2*(Hr*cos - Hi*sin)
    for (int ky = 1; ky < MD; ky++) {
        u64 cp[4], sp[4];
#pragma unroll
        for (int p = 0; p < 4; p++) {
            int ta = (ky * (v0 + 2 * p)) & 255;
            int tb = (ta + ky) & 255;
            cp[p] = pack2(cs2[ta], cs2[tb]);
            sp[p] = pack2(ns2[ta], ns2[tb]);
        }
        const float* hrp = Hr + ky * 64 + o0;
        const float* hip = Hi + ky * 64 + o0;
#pragma unroll
        for (int k = 0; k < 8; k++) {
            u64 hrd = pack2(hrp[k], hrp[k]);
            u64 hid = pack2(hip[k], hip[k]);
#pragma unroll
            for (int p = 0; p < 4; p++) {
                acc[p][k] = fma2(hrd, cp[p], acc[p][k]);
                acc[p][k] = fma2(hid, sp[p], acc[p][k]);
            }
        }
    }

    // SiLU + store (float4)
    float* ob = out + (((size_t)(b * RR + u) * RR) + v0) * CO + o0;
#pragma unroll
    for (int p = 0; p < 4; p++) {
        float lo[8], hi[8];
#pragma unroll
        for (int k = 0; k < 8; k++) unpack2(acc[p][k], lo[k], hi[k]);
        float* r0 = ob + (size_t)(2 * p) * CO;
        float* r1 = ob + (size_t)(2 * p + 1) * CO;
        *(float4*)r0 = make_float4(silu_f(lo[0]), silu_f(lo[1]), silu_f(lo[2]), silu_f(lo[3]));
        *(float4*)(r0 + 4) = make_float4(silu_f(lo[4]), silu_f(lo[5]), silu_f(lo[6]), silu_f(lo[7]));
        *(float4*)r1 = make_float4(silu_f(hi[0]), silu_f(hi[1]), silu_f(hi[2]), silu_f(hi[3]));
        *(float4*)(r1 + 4) = make_float4(silu_f(hi[4]), silu_f(hi[5]), silu_f(hi[6]), silu_f(hi[7]));
    }
}

// ---------------------------------------------------------------------------
// Launcher
// ---------------------------------------------------------------------------
extern "C" void kernel_launch(void* const* d_in, const int* in_sizes, int n_in,
                              void* d_out, int out_size) {
    const float* X = (const float*)d_in[0];
    const float* Wres = (const float*)d_in[1];
    const float* bres = (const float*)d_in[2];
    const float* fw0 = (const float*)d_in[3];
    const float* fw1 = (const float*)d_in[4];
    float* out = (float*)d_out;

    cudaFuncSetAttribute(k5_final, cudaFuncAttributeMaxDynamicSharedMemorySize,
                         SM5_TOT * (int)sizeof(float));

    k1_coldft<<<dim3(RR, NB), 256>>>(X);
    k2_rowdft<<<dim3(MD, NB, 2), 256>>>();
    k3_mix<<<dim3(KXN, MD), 256>>>(fw0, fw1);
    k4_invrow<<<dim3(MD, NB, 4), 256>>>();
    k5_final<<<dim3(RR, NB), 256, SM5_TOT * (int)sizeof(float)>>>(X, Wres, bres, out);
}

// round 14
// speedup vs baseline: 1.3662x; 1.0595x over previous
#include <cuda_runtime.h>
#include <cstdint>

// Problem constants
#define NB 8
#define RR 256
#define CI 64
#define CO 64
#define MD 16
#define KXN 32  // 16 top + 16 bottom kx modes

typedef unsigned long long u64;

// ---------------------------------------------------------------------------
// Scratch (device globals -- no allocation allowed)
// ---------------------------------------------------------------------------
__device__ float2 g_A[NB * MD * RR * CI];   // [b][ky][u][i]   16.8 MB
__device__ float2 g_F[NB * KXN * MD * CI];  // [b][kx][ky][i]   2.1 MB
__device__ float2 g_G[NB * KXN * MD * CO];  // [b][kx][ky][o]   2.1 MB
__device__ float2 g_H[NB * MD * RR * CO];   // [b][ky][u][o]   16.8 MB

// ---------------------------------------------------------------------------
// Packed f32x2 helpers (Blackwell dual-FP32 pipe; only reachable via PTX)
// ---------------------------------------------------------------------------
__device__ __forceinline__ u64 pack2(float lo, float hi) {
    u64 r;
    asm("mov.b64 %0, {%1,%2};" : "=l"(r) : "f"(lo), "f"(hi));
    return r;
}
__device__ __forceinline__ u64 fma2(u64 a, u64 b, u64 c) {
    u64 r;
    asm("fma.rn.f32x2 %0, %1, %2, %3;" : "=l"(r) : "l"(a), "l"(b), "l"(c));
    return r;
}
__device__ __forceinline__ u64 add2(u64 a, u64 b) {
    u64 r;
    asm("add.rn.f32x2 %0, %1, %2;" : "=l"(r) : "l"(a), "l"(b));
    return r;
}
__device__ __forceinline__ void unpack2(u64 v, float& lo, float& hi) {
    asm("mov.b64 {%0,%1}, %2;" : "=f"(lo), "=f"(hi) : "l"(v));
}

__device__ __forceinline__ float silu_f(float x) {
    float e = __expf(-x);
    return __fdividef(x, 1.0f + e);
}

// ---------------------------------------------------------------------------
// K1: partial column DFT along v for ky = 0..15. (R7 version, verified.)
// ---------------------------------------------------------------------------
__global__ __launch_bounds__(256) void k1_coldft(const float* __restrict__ X) {
    __shared__ u64 csd[256];  // (c, c)
    __shared__ u64 snd[256];  // (-s, -s)
    int tid = threadIdx.x;
    {
        float s, c;
        sincospif((float)tid * (1.0f / 128.0f), &s, &c);  // angle 2*pi*tid/256
        csd[tid] = pack2(c, c);
        snd[tid] = pack2(-s, -s);
    }
    __syncthreads();

    int u = blockIdx.x, b = blockIdx.y;
    int lane = tid & 31, g = tid >> 5;
    int ky0 = 2 * g, ky1 = 2 * g + 1;
    const u64* xr = (const u64*)(X + ((size_t)(b * RR + u) * RR) * CI) + lane;

    u64 one = pack2(1.0f, 1.0f), mone = pack2(-1.0f, -1.0f);
    u64 x0 = xr[0];
    u64 x128 = xr[128 * 32];
    u64 ar0 = fma2(x128, one, x0);   // ky even: x0 + x128
    u64 ar1 = fma2(x128, mone, x0);  // ky odd:  x0 - x128
    u64 ai0 = pack2(0.0f, 0.0f), ai1 = ai0;

    int t0 = 0, t1 = 0;
#pragma unroll 4
    for (int v = 1; v <= 127; ++v) {
        u64 xa = xr[v * 32];
        u64 xb = xr[(256 - v) * 32];
        u64 smv = add2(xa, xb);
        u64 dfv = fma2(xb, mone, xa);
        t0 = (t0 + ky0) & 255;  // ky0 * v
        t1 = (t1 + ky1) & 255;  // ky1 * v
        ar0 = fma2(smv, csd[t0], ar0);
        ai0 = fma2(dfv, snd[t0], ai0);
        ar1 = fma2(smv, csd[t1], ar1);
        ai1 = fma2(dfv, snd[t1], ai1);
    }

    float4* a4 = (float4*)g_A;
    float rl, rh, il, ih;
    unpack2(ar0, rl, rh); unpack2(ai0, il, ih);
    a4[((size_t)(b * MD + ky0) * RR + u) * 32 + lane] = make_float4(rl, il, rh, ih);
    unpack2(ar1, rl, rh); unpack2(ai1, il, ih);
    a4[((size_t)(b * MD + ky1) * RR + u) * 32 + lane] = make_float4(rl, il, rh, ih);
}

// ---------------------------------------------------------------------------
// K2: partial row DFT along u, conjugate-paired modes + Chebyshev-over-u.
// Pair slot k (1..16): top idx k (kx=k, k<=15), bottom idx 32-k (kx=-k).
//   P=sum prs*c_k(u), Q=sum mis*s_k(u), R=sum pis*c_k(u), S=sum mrs*s_k(u)
//   top F=(P+Q, R-S), bottom F=(P-Q, R+S); u=0/128 terms add to P,R with
//   sign (-1)^k. Mode 0 = (P0,R0)+u0/u128 terms, stored by g==0.
// Twiddles advance by Chebyshev recurrence over sequential u (no tables,
// no index ALU in the loop). 4 pair slots/thread -> 16+20 regs, no spill
// (the R9 failure was 68 accumulators; this layout avoids it).
// ---------------------------------------------------------------------------
__global__ __launch_bounds__(256) void k2_rowdft() {
    __shared__ float2 tw[256];  // (cos, sin) of 2*pi*t/256
    int tid = threadIdx.x;
    {
        float s, c;
        sincospif((float)tid * (1.0f / 128.0f), &s, &c);
        tw[tid] = make_float2(c, s);
    }
    __syncthreads();

    int ky = blockIdx.x, b = blockIdx.y;
    int i = tid & 63, g = tid >> 6;   // pair slots 4g+1 .. 4g+4
    const float2* ap = g_A + ((size_t)(b * MD + ky) * RR) * CI + i;

    float P[4] = {0, 0, 0, 0}, Q[4] = {0, 0, 0, 0};
    float R[4] = {0, 0, 0, 0}, S[4] = {0, 0, 0, 0};
    float P0 = 0.f, R0 = 0.f;
    float cc[4], sc[4], cp[4], sp_[4], tc[4];
#pragma unroll
    for (int m = 0; m < 4; m++) {
        int k = 4 * g + 1 + m;
        float2 w = tw[k];
        tc[m] = 2.0f * w.x;
        cc[m] = w.x;  sc[m] = w.y;    // state at u=1
        cp[m] = 1.0f; sp_[m] = 0.0f;  // state at u=0
    }

#pragma unroll 2
    for (int u = 1; u <= 127; ++u) {
        float2 aa = ap[u * CI];
        float2 ab = ap[(256 - u) * CI];
        float prs = aa.x + ab.x, mrs = aa.x - ab.x;
        float pis = aa.y + ab.y, mis = aa.y - ab.y;
        P0 += prs; R0 += pis;
#pragma unroll
        for (int m = 0; m < 4; m++) {
            float c = cc[m], s = sc[m];
            P[m] += prs * c; Q[m] += mis * s;
            R[m] += pis * c; S[m] += mrs * s;
            float cn = tc[m] * c - cp[m];
            float sn = tc[m] * s - sp_[m];
            cp[m] = c; sp_[m] = s;
            cc[m] = cn; sc[m] = sn;
        }
    }

    float2 a0 = ap[0];
    float2 a128 = ap[128 * CI];
#pragma unroll
    for (int m = 0; m < 4; m++) {
        int k = 4 * g + 1 + m;
        float sg = (k & 1) ? -1.0f : 1.0f;  // (-1)^k, same for top & bottom
        float Pk = P[m] + a0.x + sg * a128.x;
        float Rk = R[m] + a0.y + sg * a128.y;
        if (k <= 15)
            g_F[(((size_t)(b * KXN + k) * MD) + ky) * CI + i] =
                make_float2(Pk + Q[m], Rk - S[m]);
        g_F[(((size_t)(b * KXN + (32 - k)) * MD) + ky) * CI + i] =
            make_float2(Pk - Q[m], Rk + S[m]);
    }
    if (g == 0) {
        g_F[(((size_t)(b * KXN) * MD) + ky) * CI + i] =
            make_float2(P0 + a0.x + a128.x, R0 + a0.y + a128.y);
    }
}

// ---------------------------------------------------------------------------
// K3: channel mix (complex einsum over input channels) + ortho-norm fold.
// (R7 version, verified.)
// ---------------------------------------------------------------------------
__global__ __launch_bounds__(256) void k3_mix(const float* __restrict__ fw0,
                                              const float* __restrict__ fw1) {
    __shared__ float2 ws[CI * CO];   // 32 KB
    __shared__ float2 fs[NB][CI];    // 4 KB
    int tid = threadIdx.x;
    int kxi = blockIdx.x, ky = blockIdx.y;
    const float* src = (kxi < 16) ? fw0 : fw1;
    int x = (kxi < 16) ? kxi : (kxi - 16);

    for (int p = tid; p < CI * CO; p += 256) {
        int i = p >> 6, o = p & 63;
        ws[p] = *(const float2*)(src + ((((size_t)i * CO + o) * MD + x) * MD + ky) * 2);
    }
    for (int p = tid; p < NB * CI; p += 256) {
        int bb = p >> 6, i = p & 63;
        fs[bb][i] = g_F[(((size_t)(bb * KXN + kxi) * MD) + ky) * CI + i];
    }
    __syncthreads();

    int o = tid & 63, bg = tid >> 6;
    const float scale = 1.0f / 65536.0f;  // ortho norm (1/256 fwd * 1/256 inv)
    for (int bb = bg; bb < NB; bb += 4) {
        float Gr = 0.f, Gi = 0.f;
#pragma unroll 8
        for (int i = 0; i < CI; i++) {
            float2 f = fs[bb][i];
            float2 w = ws[i * CO + o];
            Gr += f.x * w.x - f.y * w.y;
            Gi += f.x * w.y + f.y * w.x;
        }
        g_G[(((size_t)(bb * KXN + kxi) * MD) + ky) * CO + o] =
            make_float2(Gr * scale, Gi * scale);
    }
}

// ---------------------------------------------------------------------------
// K4: inverse DFT along kx, conjugate-paired modes + u-pair symmetry +
// Chebyshev twiddles. (R9/R10 version, verified 14.1us.)
// ---------------------------------------------------------------------------
__global__ __launch_bounds__(256) void k4_invrow() {
    __shared__ float2 tw[256];
    __shared__ float2 a1[17 * 64];   // (Sx, Sy)
    __shared__ float2 a2[17 * 64];   // (Dy, Dx)
    int tid = threadIdx.x;
    {
        float s, c;
        sincospif((float)tid * (1.0f / 128.0f), &s, &c);
        tw[tid] = make_float2(c, s);
    }
    int ky = blockIdx.x, b = blockIdx.y;
    const float2* gp = g_G + ((size_t)(b * KXN) * MD + ky) * CO;  // idx stride MD*CO
    for (int p = tid; p < 17 * 64; p += 256) {
        int k = p >> 6, o = p & 63;
        float2 gt = (k < 16) ? gp[(size_t)k * MD * CO + o] : make_float2(0.f, 0.f);
        float2 gb = (k >= 1) ? gp[(size_t)(32 - k) * MD * CO + o] : make_float2(0.f, 0.f);
        a1[p] = make_float2(gt.x + gb.x, gt.y + gb.y);
        a2[p] = make_float2(gt.y - gb.y, gt.x - gb.x);
    }
    __syncthreads();

    int o = tid & 63, grp = tid >> 6;
    int base = blockIdx.z * 32 + grp * 8;
    int nIter = (base == 0) ? 9 : 8;     // warp-uniform (tid<64 of z==0)
    float2* hp = g_H + ((size_t)(b * MD + ky) * RR) * CO + o;
    const float2* a1p = a1 + o;
    const float2* a2p = a2 + o;

#pragma unroll 2
    for (int it = 0; it < nIter; it++) {
        int u = (it == 8) ? 128 : (base + it);
        float2 w1 = tw[u];
        float c1 = w1.x, s1 = w1.y;
        float tc = 2.0f * c1;
        float2 v0 = a1p[0];
        float Pc = v0.x, Qc = v0.y, Ps = 0.f, Qs = 0.f;
        float2 x1 = a1p[64], y1 = a2p[64];
        Pc += x1.x * c1; Qc += x1.y * c1;
        Ps += y1.x * s1; Qs += y1.y * s1;
        float ckm2 = 1.f, ckm1 = c1, skm2 = 0.f, skm1 = s1;
#pragma unroll
        for (int k = 2; k <= 16; k++) {
            float ck = tc * ckm1 - ckm2;
            float sk = tc * skm1 - skm2;
            float2 xk = a1p[k * 64], yk = a2p[k * 64];
            Pc += xk.x * ck; Qc += xk.y * ck;
            Ps += yk.x * sk; Qs += yk.y * sk;
            ckm2 = ckm1; ckm1 = ck;
            skm2 = skm1; skm1 = sk;
        }
        int um = (u == 0) ? 0 : (256 - u);
        hp[(size_t)u * CO]  = make_float2(Pc - Ps, Qc + Qs);
        hp[(size_t)um * CO] = make_float2(Pc + Ps, Qc - Qs);
    }
}

// ---------------------------------------------------------------------------
// K5: fused inverse real-DFT along ky + residual GEMM + SiLU.
// R7-verified core; CHANGE: Hr/Hi stored pre-duplicated as u64 with a bank
// swizzle (slot = ky*64 + (o&7)*8 + (o>>3)) so the ky-loop does 16
// conflict-free LDS.64 instead of 16 LDS.32 + 16 packs.
// Shared: Xpair[128*67] u64 | Hrd[1024] u64 | Hid[1024] u64 | floats:
//   cs2[256] ns2[256] Ws[4096] br[64]   (= 103,680 bytes; x2 blocks fits)
// ---------------------------------------------------------------------------
#define XP_STRIDE 67
#define HRD_U64 (128 * XP_STRIDE)            // 8576
#define HID_U64 (HRD_U64 + MD * CO)          // 9600
#define F_BASE ((HID_U64 + MD * CO) * 2)     // float index 21248
#define SM5_CS F_BASE
#define SM5_NS (SM5_CS + 256)
#define SM5_WS (SM5_NS + 256)
#define SM5_BR (SM5_WS + 4096)
#define SM5_TOT (SM5_BR + 64)                // 25920 floats = 103680 bytes

__global__ __launch_bounds__(256, 2) void k5_final(const float* __restrict__ X,
                                                   const float* __restrict__ Wres,
                                                   const float* __restrict__ bres,
                                                   float* __restrict__ out) {
    extern __shared__ float sm[];
    u64* Xp = (u64*)sm;
    u64* Hrd = (u64*)sm + HRD_U64;
    u64* Hid = (u64*)sm + HID_U64;
    float* cs2 = sm + SM5_CS;
    float* ns2 = sm + SM5_NS;
    float* Ws = sm + SM5_WS;
    float* br = sm + SM5_BR;

    int tid = threadIdx.x;
    int u = blockIdx.x, b = blockIdx.y;

    {
        float s, c;
        sincospif((float)tid * (1.0f / 128.0f), &s, &c);
        cs2[tid] = 2.0f * c;   // factor 2 folded (Hermitian pairs)
        ns2[tid] = -2.0f * s;
    }
    if (tid < 64) br[tid] = bres[tid];
    {
        const float4* w4 = (const float4*)Wres;
        float4* ws4 = (float4*)Ws;
        for (int p = tid; p < 1024; p += 256) ws4[p] = w4[p];
    }
    {
        // Xpair[vp][c] = (X[2vp][c], X[2vp+1][c]) as u64, stride XP_STRIDE.
        const float4* x4 = (const float4*)(X + ((size_t)(b * RR + u) * RR) * CI);
        for (int p = tid; p < 4096; p += 256) {
            float4 xv = x4[p];
            int v = p >> 4;            // 16 float4 per v-row
            int cq = (p & 15) * 4;
            float* base = (float*)(Xp + (size_t)(v >> 1) * XP_STRIDE + cq) + (v & 1);
            base[0] = xv.x; base[2] = xv.y; base[4] = xv.z; base[6] = xv.w;
        }
    }
    for (int p = tid; p < MD * CO; p += 256) {
        int ky = p >> 6, o = p & 63;
        float2 h = g_H[(((size_t)(b * MD + ky) * RR) + u) * CO + o];
        int sw = (ky << 6) + ((o & 7) << 3) + (o >> 3);  // bank swizzle
        Hrd[sw] = pack2(h.x, h.x);
        Hid[sw] = pack2(h.y, h.y);
    }
    __syncthreads();

    int vg = tid >> 3, og = tid & 7;
    int v0 = vg * 8, o0 = og * 8;
    int vp0 = vg * 4;

    u64 acc[4][8];
#pragma unroll
    for (int k = 0; k < 8; k++) {
        u64 bb = pack2(br[o0 + k], br[o0 + k]);
#pragma unroll
        for (int p = 0; p < 4; p++) acc[p][k] = bb;
    }

    // Residual GEMM: acc[p][k] over v-pair (vp0+p) x o (o0+k)
    const u64* xb = Xp + (size_t)vp0 * XP_STRIDE;
#pragma unroll 4
    for (int c = 0; c < CI; c++) {
        u64 xp0 = xb[c];
        u64 xp1 = xb[XP_STRIDE + c];
        u64 xp2 = xb[2 * XP_STRIDE + c];
        u64 xp3 = xb[3 * XP_STRIDE + c];
        const float* wr = Ws + c * 64 + o0;
        float4 wa = *(const float4*)wr;
        float4 wb = *(const float4*)(wr + 4);
        float wv[8] = {wa.x, wa.y, wa.z, wa.w, wb.x, wb.y, wb.z, wb.w};
#pragma unroll
        for (int k = 0; k < 8; k++) {
            u64 wd = pack2(wv[k], wv[k]);
            acc[0][k] = fma2(xp0, wd, acc[0][k]);
            acc[1][k] = fma2(xp1, wd, acc[1][k]);
            acc[2][k] = fma2(xp2, wd, acc[2][k]);
            acc[3][k] = fma2(xp3, wd, acc[3][k]);
        }
    }

    // Spectral ky = 0 term: + Re(H0[o]) (DC imag discarded, matches irfft)
    {
        const u64* h0p = Hrd + og;  // slot k*8 + og
#pragma unroll
        for (int k = 0; k < 8; k++) {
            u64 h0 = h0p[k * 8];
#pragma unroll
            for (int p = 0; p < 4; p++) acc[p][k] = add2(acc[p][k], h0);
        }
    }

    // Spectral ky = 1..15: + 2*(Hr*cos - Hi*sin)
    for (int ky = 1; ky < MD; ky++) {
        u64 cp[4], sp[4];
#pragma unroll
        for (int p = 0; p < 4; p++) {
            int ta = (ky * (v0 + 2 * p)) & 255;
            int tb = (ta + ky) & 255;
            cp[p] = pack2(cs2[ta], cs2[tb]);
            sp[p] = pack2(ns2[ta], ns2[tb]);
        }
        const u64* hrp = Hrd + (ky << 6) + og;
        const u64* hip = Hid + (ky << 6) + og;
#pragma unroll
        for (int k = 0; k < 8; k++) {
            u64 hrd = hrp[k * 8];
            u64 hid = hip[k * 8];
#pragma unroll
            for (int p = 0; p < 4; p++) {
                acc[p][k] = fma2(hrd, cp[p], acc[p][k]);
                acc[p][k] = fma2(hid, sp[p], acc[p][k]);
            }
        }
    }

    // SiLU + store (float4)
    float* ob = out + (((size_t)(b * RR + u) * RR) + v0) * CO + o0;
#pragma unroll
    for (int p = 0; p < 4; p++) {
        float lo[8], hi[8];
#pragma unroll
        for (int k = 0; k < 8; k++) unpack2(acc[p][k], lo[k], hi[k]);
        float* r0 = ob + (size_t)(2 * p) * CO;
        float* r1 = ob + (size_t)(2 * p + 1) * CO;
        *(float4*)r0 = make_float4(silu_f(lo[0]), silu_f(lo[1]), silu_f(lo[2]), silu_f(lo[3]));
        *(float4*)(r0 + 4) = make_float4(silu_f(lo[4]), silu_f(lo[5]), silu_f(lo[6]), silu_f(lo[7]));
        *(float4*)r1 = make_float4(silu_f(hi[0]), silu_f(hi[1]), silu_f(hi[2]), silu_f(hi[3]));
        *(float4*)(r1 + 4) = make_float4(silu_f(hi[4]), silu_f(hi[5]), silu_f(hi[6]), silu_f(hi[7]));
    }
}

// ---------------------------------------------------------------------------
// Launcher
// ---------------------------------------------------------------------------
extern "C" void kernel_launch(void* const* d_in, const int* in_sizes, int n_in,
                              void* d_out, int out_size) {
    const float* X = (const float*)d_in[0];
    const float* Wres = (const float*)d_in[1];
    const float* bres = (const float*)d_in[2];
    const float* fw0 = (const float*)d_in[3];
    const float* fw1 = (const float*)d_in[4];
    float* out = (float*)d_out;

    cudaFuncSetAttribute(k5_final, cudaFuncAttributeMaxDynamicSharedMemorySize,
                         SM5_TOT * (int)sizeof(float));

    k1_coldft<<<dim3(RR, NB), 256>>>(X);
    k2_rowdft<<<dim3(MD, NB), 256>>>();
    k3_mix<<<dim3(KXN, MD), 256>>>(fw0, fw1);
    k4_invrow<<<dim3(MD, NB, 4), 256>>>();
    k5_final<<<dim3(RR, NB), 256, SM5_TOT * (int)sizeof(float)>>>(X, Wres, bres, out);
}